// round 7
// baseline (speedup 1.0000x reference)
#include <cuda_runtime.h>
#include <math.h>

// 21-qubit / 3-layer QNN statevector sim. State in "pair format":
//   d_state[h] = float4(re(2h), re(2h+1), im(2h), im(2h+1)),  h = 20-bit pair idx.
// amp bit k <-> qubit (20-k); amp bit 0 = float4 lane; pair bit k = amp bit k+1.
// passA: Rots amps 0..11 + CNOT targets 0..9 (perm + lane swap at store);
//        TILE = pair bits 0..10 (2048 pairs), 4 pairs/thread, 3 CTAs/SM.
// passB: Rots amps 12..20 + CNOT targets 10..19 (perm at store);
//        TILE = pair bit 0 + pair bits 9..19 (4096 pairs), 8 pairs/thread.
// Warp-shuffle gates handle lane-resident bits; each pass = 2 rounds, 1 smem trip.

#define NQ        21
#define NPAIR     (1u << 20)

#define THREADS_A 512
#define TILEP_A   2048
#define SMEMB_A   (TILEP_A * 16 + 768)
#define NBLK_A    512

#define THREADS_B 512
#define TILEP_B   4096
#define SMEMB_B   (TILEP_B * 16 + 768)
#define NBLK_B    256

typedef unsigned long long u64;

__device__ float4 d_state[NPAIR];

struct Gate2 { u64 p, q, mq, r, mr, s, ms; };
__device__ Gate2 d_gates[3][NQ];

__device__ __forceinline__ u64 fma2(u64 a, u64 b, u64 c) {
    u64 d; asm("fma.rn.f32x2 %0,%1,%2,%3;" : "=l"(d) : "l"(a), "l"(b), "l"(c)); return d;
}
__device__ __forceinline__ u64 mul2(u64 a, u64 b) {
    u64 d; asm("mul.rn.f32x2 %0,%1,%2;" : "=l"(d) : "l"(a), "l"(b)); return d;
}
__device__ __forceinline__ float flo(u64 v) { return __uint_as_float((unsigned)v); }
__device__ __forceinline__ float fhi(u64 v) { return __uint_as_float((unsigned)(v >> 32)); }
__device__ __forceinline__ u64 fpack(float a, float b) {
    return (u64)__float_as_uint(a) | ((u64)__float_as_uint(b) << 32);
}

__global__ void prep_gates(const float* __restrict__ param, float* __restrict__ out) {
    int t = threadIdx.x;
    if (t == 0) out[0] = 0.f;
    if (t >= 3 * NQ) return;
    int layer = t / NQ, bit = t % NQ, qubit = 20 - bit;
    const float* pp = param + (layer * NQ + qubit) * 3;
    float phi = pp[0], th = pp[1], om = pp[2];
    float s, c;   sincosf(0.5f * th, &s, &c);
    float sa, ca; sincosf(0.5f * (phi + om), &sa, &ca);
    float sb, cb; sincosf(0.5f * (phi - om), &sb, &cb);
    // u00=(p,q)  u01=(r,s)  u10=(-r,s)  u11=(p,-q)
    float p = ca * c, q = -sa * c, r = -cb * s, sv = -sb * s;
    Gate2 g;
    g.p  = fpack(p, p);    g.q  = fpack(q, q);   g.mq = fpack(-q, -q);
    g.r  = fpack(r, r);    g.mr = fpack(-r, -r);
    g.s  = fpack(sv, sv);  g.ms = fpack(-sv, -sv);
    d_gates[layer][bit] = g;
}

// Paired-register gate on register-index bit S.
template<int S, int N>
__device__ __forceinline__ void vgate(u64 (&re)[N], u64 (&im)[N], const u64* __restrict__ g) {
    const u64 p = g[0], q = g[1], mq = g[2], r = g[3], mr = g[4], s = g[5], ms = g[6];
#pragma unroll
    for (int j = 0; j < N; j++) {
        if (j & S) continue;
        const int j1 = j | S;
        u64 xr = re[j], xi = im[j], yr = re[j1], yi = im[j1];
        u64 nr0 = fma2(ms, yi, fma2(r,  yr, fma2(mq, xi, mul2(p,  xr))));
        u64 ni0 = fma2(r,  yi, fma2(s,  yr, fma2(p,  xi, mul2(q,  xr))));
        u64 nr1 = fma2(q,  yi, fma2(p,  yr, fma2(ms, xi, mul2(mr, xr))));
        u64 ni1 = fma2(p,  yi, fma2(mq, yr, fma2(mr, xi, mul2(s,  xr))));
        re[j] = nr0; im[j] = ni0; re[j1] = nr1; im[j1] = ni1;
    }
}

// Warp-shuffle gate on lane bit B of threadIdx.
template<int B, int N>
__device__ __forceinline__ void hgate(u64 (&re)[N], u64 (&im)[N], const u64* __restrict__ g) {
    const u64 p = g[0], s = g[5], ms = g[6];
    const bool hi = (threadIdx.x >> B) & 1;
    const u64 A  = hi ? g[1] : g[2];   //  q : -q
    const u64 C  = hi ? g[2] : g[1];   // -q :  q
    const u64 Bc = hi ? g[4] : g[3];   // -r :  r
#pragma unroll
    for (int j = 0; j < N; j++) {
        u64 wr = __shfl_xor_sync(0xffffffffu, re[j], 1 << B);
        u64 wi = __shfl_xor_sync(0xffffffffu, im[j], 1 << B);
        u64 nr = fma2(ms, wi, fma2(Bc, wr, fma2(A, im[j], mul2(p, re[j]))));
        u64 ni = fma2(Bc, wi, fma2(s,  wr, fma2(p, im[j], mul2(C, re[j]))));
        re[j] = nr; im[j] = ni;
    }
}

// Scalar gate on amp bit 0 (inside the f32x2 lane).
template<int N>
__device__ __forceinline__ void sgate(u64 (&re)[N], u64 (&im)[N], const u64* __restrict__ g) {
    const float p = flo(g[0]), q = flo(g[1]), r = flo(g[3]), s = flo(g[5]);
#pragma unroll
    for (int j = 0; j < N; j++) {
        float xr = flo(re[j]), yr = fhi(re[j]), xi = flo(im[j]), yi = fhi(im[j]);
        float nr0 =  p * xr - q * xi + r * yr - s * yi;
        float ni0 =  q * xr + p * xi + s * yr + r * yi;
        float nr1 = -r * xr - s * xi + p * yr + q * yi;
        float ni1 =  s * xr - r * xi - q * yr + p * yi;
        re[j] = fpack(nr0, nr1); im[j] = fpack(ni0, ni1);
    }
}

__device__ __forceinline__ float4 packf4(u64 r, u64 i) {
    return make_float4(flo(r), fhi(r), flo(i), fhi(i));
}
__device__ __forceinline__ void unpackf4(float4 v, u64& r, u64& i) {
    r = fpack(v.x, v.y); i = fpack(v.z, v.w);
}

// ============================ pass A ============================
// tile = pair bits 0..10; swizzle separates r2's lane-varying bits {0,1,2,7,8}.
__device__ __forceinline__ unsigned swA(unsigned l) {
    return l ^ ((l >> 3) & 7u) ^ (((l >> 7) & 3u) << 3);
}
// r2 layout: t0..2->l0..2, t5,t6->l3,l4, j->l5,l6, t3,t4->l7,l8, t7,t8->l9,l10
__device__ __forceinline__ unsigned r2a(unsigned t, unsigned j) {
    return (t & 7u) | (((t >> 5) & 3u) << 3) | (j << 5)
         | (((t >> 3) & 3u) << 7) | ((t >> 7) << 9);
}

template<int LAYER, bool FIRST>
__global__ void __launch_bounds__(THREADS_A, 3)
passA_kernel(const float* __restrict__ feat) {
    extern __shared__ char smraw[];
    float4* sm = reinterpret_cast<float4*>(smraw);
    u64* gsm = reinterpret_cast<u64*>(smraw + TILEP_A * 16);
    const unsigned t  = threadIdx.x;
    const unsigned gp = blockIdx.x << 11;
    u64 re[4], im[4];

    // stage gate table: amps 0..11 = 12 gates x 7 u64
    {
        const u64* src = reinterpret_cast<const u64*>(d_gates) + (LAYER * NQ) * 7;
        if (t < 84) gsm[t] = src[t];
    }

    // r1 (global): l = t | (j<<9); lanes = pairs 0..4, j = pairs 9,10
#pragma unroll
    for (int j = 0; j < 4; j++) {
        unsigned l = t | (j << 9);
        if (FIRST) {
            float2 fv = reinterpret_cast<const float2*>(feat)[gp | l];
            re[j] = fpack(fv.x, fv.y); im[j] = 0ull;
        } else {
            unpackf4(d_state[gp | l], re[j], im[j]);
        }
    }
    __syncthreads();                      // gate table visible

    sgate(re, im, gsm + 0 * 7);           // amp 0
    hgate<0>(re, im, gsm + 1 * 7);        // amp 1
    hgate<1>(re, im, gsm + 2 * 7);        // amp 2
    hgate<2>(re, im, gsm + 3 * 7);        // amp 3
    hgate<3>(re, im, gsm + 4 * 7);        // amp 4
    hgate<4>(re, im, gsm + 5 * 7);        // amp 5
    vgate<1>(re, im, gsm + 10 * 7);       // amp 10 (pair 9 = j bit 0)
    vgate<2>(re, im, gsm + 11 * 7);       // amp 11 (pair 10 = j bit 1)
#pragma unroll
    for (int j = 0; j < 4; j++) sm[swA(t | (j << 9))] = packf4(re[j], im[j]);
    __syncthreads();

    // r2: j = pairs 5,6 (amps 6,7); lane bits 3,4 -> pairs 7,8 (amps 8,9)
#pragma unroll
    for (int j = 0; j < 4; j++) unpackf4(sm[swA(r2a(t, j))], re[j], im[j]);
    vgate<1>(re, im, gsm + 6 * 7);        // amp 6
    vgate<2>(re, im, gsm + 7 * 7);        // amp 7
    hgate<3>(re, im, gsm + 8 * 7);        // amp 8
    hgate<4>(re, im, gsm + 9 * 7);        // amp 9

    // CNOT perm (targets amps 0..9) inverse-folded into the store + lane swap
#pragma unroll
    for (int j = 0; j < 4; j++) {
        unsigned l = r2a(t, j);
        unsigned u = l ^ ((l >> 1) & 0x155u);
        unsigned h = u ^ ((u >> 1) & 0xAAu);
        float4 v = packf4(re[j], im[j]);
        d_state[gp | h] = (h & 1u) ? make_float4(v.y, v.x, v.w, v.z) : v;
    }
}

// ============================ pass B ============================
// tile local bits: 0 = pair 0 (amp1 spectator); 1..11 = pairs 9..19 (amps 10..20).
__device__ __forceinline__ unsigned gpair(unsigned l, unsigned blk) {
    return (l & 1u) | (blk << 1) | ((l >> 1) << 9);
}
__device__ __forceinline__ unsigned swB(unsigned l) { return l ^ ((l >> 3) & 7u); }
// r2 layout: t0..3->l0..3, t5->l4, j->l5..7, t4->l8, t6..8->l9..11
__device__ __forceinline__ unsigned r2b(unsigned t, unsigned j) {
    return (t & 15u) | (((t >> 5) & 1u) << 4) | (j << 5)
         | (((t >> 4) & 1u) << 8) | ((t >> 6) << 9);
}

template<int LAYER, bool LAST>
__global__ void __launch_bounds__(THREADS_B, 2)
passB_kernel(float* __restrict__ out) {
    extern __shared__ char smraw[];
    float4* sm = reinterpret_cast<float4*>(smraw);
    u64* gsm = reinterpret_cast<u64*>(smraw + TILEP_B * 16);
    const unsigned t = threadIdx.x;
    const unsigned blk = blockIdx.x;
    u64 re[8], im[8];

    // stage gate table: amps 12..20 = 9 gates x 7 u64
    {
        const u64* src = reinterpret_cast<const u64*>(d_gates) + (LAYER * NQ + 12) * 7;
        if (t < 63) gsm[t] = src[t];
    }

    // r1 (global): l = t | (j<<9); lane bits 3,4 = pairs 11,12 (amps 12,13);
    // j = local 9,10,11 = pairs 17,18,19 (amps 18,19,20)
#pragma unroll
    for (int j = 0; j < 8; j++)
        unpackf4(d_state[gpair(t | (j << 9), blk)], re[j], im[j]);
    __syncthreads();                      // gate table visible

    hgate<3>(re, im, gsm + 0 * 7);        // amp 12
    hgate<4>(re, im, gsm + 1 * 7);        // amp 13
    vgate<1>(re, im, gsm + 6 * 7);        // amp 18
    vgate<2>(re, im, gsm + 7 * 7);        // amp 19
    vgate<4>(re, im, gsm + 8 * 7);        // amp 20
#pragma unroll
    for (int j = 0; j < 8; j++) sm[swB(t | (j << 9))] = packf4(re[j], im[j]);
    __syncthreads();

    // r2: j = local 5,6,7 = amps 14,15,16; lane bit 4 -> local 8 = amp 17
#pragma unroll
    for (int j = 0; j < 8; j++) unpackf4(sm[swB(r2b(t, j))], re[j], im[j]);
    vgate<1>(re, im, gsm + 2 * 7);        // amp 14
    vgate<2>(re, im, gsm + 3 * 7);        // amp 15
    vgate<4>(re, im, gsm + 4 * 7);        // amp 16
    hgate<4>(re, im, gsm + 5 * 7);        // amp 17

    if (LAST) {
        // Perm is a bijection not touching amp bit 0 -> skip it; sum lo lanes.
        float acc = 0.f;
#pragma unroll
        for (int j = 0; j < 8; j++) {
            float rr = flo(re[j]), ii = flo(im[j]);
            acc += rr * rr + ii * ii;
        }
#pragma unroll
        for (int o = 16; o > 0; o >>= 1)
            acc += __shfl_xor_sync(0xffffffffu, acc, o);
        __syncthreads();
        float* red = reinterpret_cast<float*>(sm);
        if ((t & 31u) == 0) red[t >> 5] = acc;
        __syncthreads();
        if (t == 0) {
            float v = 0.f;
#pragma unroll
            for (int w = 0; w < THREADS_B / 32; w++) v += red[w];
            atomicAdd(out, v);
        }
        return;
    }

    // CNOT perm (targets amps 10..19 = local bits 1..10) inverse-folded into store
#pragma unroll
    for (int j = 0; j < 8; j++) {
        unsigned l = r2b(t, j);
        unsigned u = l ^ ((l >> 1) & 0x554u);
        unsigned h = u ^ ((u >> 1) & 0x2AAu);
        d_state[gpair(h, blk)] = packf4(re[j], im[j]);
    }
}

extern "C" void kernel_launch(void* const* d_in, const int* in_sizes, int n_in,
                              void* d_out, int out_size) {
    const float* feat  = (const float*)d_in[0];
    const float* param = (const float*)d_in[1];
    float* out = (float*)d_out;

    cudaFuncSetAttribute(passA_kernel<0, true >, cudaFuncAttributeMaxDynamicSharedMemorySize, SMEMB_A);
    cudaFuncSetAttribute(passA_kernel<1, false>, cudaFuncAttributeMaxDynamicSharedMemorySize, SMEMB_A);
    cudaFuncSetAttribute(passA_kernel<2, false>, cudaFuncAttributeMaxDynamicSharedMemorySize, SMEMB_A);
    cudaFuncSetAttribute(passB_kernel<0, false>, cudaFuncAttributeMaxDynamicSharedMemorySize, SMEMB_B);
    cudaFuncSetAttribute(passB_kernel<1, false>, cudaFuncAttributeMaxDynamicSharedMemorySize, SMEMB_B);
    cudaFuncSetAttribute(passB_kernel<2, true >, cudaFuncAttributeMaxDynamicSharedMemorySize, SMEMB_B);

    prep_gates<<<1, 64>>>(param, out);
    passA_kernel<0, true ><<<NBLK_A, THREADS_A, SMEMB_A>>>(feat);
    passB_kernel<0, false><<<NBLK_B, THREADS_B, SMEMB_B>>>(out);
    passA_kernel<1, false><<<NBLK_A, THREADS_A, SMEMB_A>>>(feat);
    passB_kernel<1, false><<<NBLK_B, THREADS_B, SMEMB_B>>>(out);
    passA_kernel<2, false><<<NBLK_A, THREADS_A, SMEMB_A>>>(feat);
    passB_kernel<2, true ><<<NBLK_B, THREADS_B, SMEMB_B>>>(out);
}